// round 14
// baseline (speedup 1.0000x reference)
#include <cuda_runtime.h>
#include <cuda_fp16.h>
#include <math.h>
#include <stdint.h>

#define NE   8
#define HD   1024
#define DD   512
#define DS   1024
#define TMAX 8192

#define BM 128
#define BN 64
#define BK 32
#define SA 40                    // A: 16-bit elems per row (32 + 8 pad)
#define SB 72                    // B: 16-bit elems per row (64 + 8 pad)
#define TILE_A (128 * SA * 2)    // 10240 B
#define TILE_BB (32 * SB * 2)    // 4608 B
#define STG_GU (TILE_A + 2 * TILE_BB)   // 19456
#define STG_DN (TILE_A + TILE_BB)       // 14848
#define SMEM_GU (4 * STG_GU)     // 77824 -> 2 CTAs/SM
#define SMEM_DN (4 * STG_DN)     // 59392 -> 2 CTAs/SM

// ---------------- scratch (static device globals; no allocations) ------------
__device__ __align__(16) __half g_xh[(size_t)TMAX * HD];
__device__ __align__(16) __half g_bufH[(size_t)NE * TMAX * DD];   // routed gu out
__device__ __align__(16) __half g_buf2H[(size_t)TMAX * DS];       // shared gu out
__device__ __align__(16) __half g_routed[(size_t)2 * TMAX * HD];  // fp16 slots
// fp16 weights in NATURAL [K][N] layout
__device__ __align__(16) __half g_Wsg16[(size_t)HD * DS];
__device__ __align__(16) __half g_Wsu16[(size_t)HD * DS];
__device__ __align__(16) __half g_Wsd16[(size_t)DS * HD];
__device__ __align__(16) __half g_Wg16[(size_t)NE * HD * DD];
__device__ __align__(16) __half g_Wu16[(size_t)NE * HD * DD];
__device__ __align__(16) __half g_Wd16[(size_t)NE * DD * HD];
__device__ int   g_cnt[NE];
__device__ int   g_tok[NE * TMAX];
__device__ int   g_slot[NE * TMAX];
__device__ float g_wt[NE * TMAX];
__device__ float g_psum[NE];

// ---------------- asm helpers ------------------------------------------------
__device__ __forceinline__ uint32_t smem_u32(const void* p) {
    uint32_t a;
    asm("{ .reg .u64 t; cvta.to.shared.u64 t, %1; cvt.u32.u64 %0, t; }" : "=r"(a) : "l"(p));
    return a;
}
#define CP16(dst, src) \
    asm volatile("cp.async.cg.shared.global [%0], [%1], 16;" :: "r"(dst), "l"(src) : "memory")
#define CPCOMMIT() asm volatile("cp.async.commit_group;" ::: "memory")
#define CPWAIT2()  asm volatile("cp.async.wait_group 2;" ::: "memory")

__device__ __forceinline__ void ldsm4(uint32_t* r, uint32_t addr) {
    asm volatile("ldmatrix.sync.aligned.m8n8.x4.shared.b16 {%0,%1,%2,%3}, [%4];"
        : "=r"(r[0]), "=r"(r[1]), "=r"(r[2]), "=r"(r[3]) : "r"(addr));
}
__device__ __forceinline__ void ldsm4t(uint32_t* r, uint32_t addr) {
    asm volatile("ldmatrix.sync.aligned.m8n8.x4.trans.shared.b16 {%0,%1,%2,%3}, [%4];"
        : "=r"(r[0]), "=r"(r[1]), "=r"(r[2]), "=r"(r[3]) : "r"(addr));
}
__device__ __forceinline__ void mma_f16(float* c, const uint32_t* a, const uint32_t* b) {
    asm volatile(
        "mma.sync.aligned.m16n8k16.row.col.f32.f16.f16.f32 "
        "{%0,%1,%2,%3}, {%4,%5,%6,%7}, {%8,%9}, {%0,%1,%2,%3};\n"
        : "+f"(c[0]), "+f"(c[1]), "+f"(c[2]), "+f"(c[3])
        : "r"(a[0]), "r"(a[1]), "r"(a[2]), "r"(a[3]), "r"(b[0]), "r"(b[1]));
}

// ---- fused prep: z=0 split x -> fp16 (+zero counters); z=1..6 weight conv ---
__global__ void k_prep(const float* __restrict__ x, int xn4,
                       const float* __restrict__ Wsg, const float* __restrict__ Wsu,
                       const float* __restrict__ Wsd, const float* __restrict__ Wg,
                       const float* __restrict__ Wu,  const float* __restrict__ Wd) {
    const int z = blockIdx.z;
    const float* in; __half* o; size_t n4;
    if (z == 0) {
        if (blockIdx.x == 0 && threadIdx.x < NE) {
            g_cnt[threadIdx.x] = 0; g_psum[threadIdx.x] = 0.f;
        }
        in = x; o = g_xh; n4 = (size_t)xn4;
    }
    else if (z == 1) { in = Wsg; o = g_Wsg16; n4 = (size_t)HD * DS / 4; }
    else if (z == 2) { in = Wsu; o = g_Wsu16; n4 = (size_t)HD * DS / 4; }
    else if (z == 3) { in = Wsd; o = g_Wsd16; n4 = (size_t)DS * HD / 4; }
    else if (z == 4) { in = Wg;  o = g_Wg16;  n4 = (size_t)NE * HD * DD / 4; }
    else if (z == 5) { in = Wu;  o = g_Wu16;  n4 = (size_t)NE * HD * DD / 4; }
    else             { in = Wd;  o = g_Wd16;  n4 = (size_t)NE * DD * HD / 4; }
    size_t i = (size_t)blockIdx.x * blockDim.x + threadIdx.x;
    size_t stride = (size_t)gridDim.x * blockDim.x;
    for (; i < n4; i += stride) {
        float4 v = ((const float4*)in)[i];
        __half2 h01 = __floats2half2_rn(v.x, v.y);
        __half2 h23 = __floats2half2_rn(v.z, v.w);
        ((uint2*)o)[i] = make_uint2(*(uint32_t*)&h01, *(uint32_t*)&h23);
    }
}

// ---------------- router ----------------------------------------------------
__global__ void k_router(const float* __restrict__ x, const float* __restrict__ Wr, int T) {
    __shared__ float s_p[NE];
    if (threadIdx.x < NE) s_p[threadIdx.x] = 0.f;
    __syncthreads();
    int warp = blockIdx.x * (blockDim.x >> 5) + (threadIdx.x >> 5);
    int lane = threadIdx.x & 31;
    if (warp < T) {
        int t = warp;
        const float* xr = x + (size_t)t * HD;
        float acc[NE];
        #pragma unroll
        for (int e = 0; e < NE; e++) acc[e] = 0.f;
        for (int i = lane; i < HD; i += 32) {
            float xv = xr[i];
            const float* w = Wr + (size_t)i * NE;
            #pragma unroll
            for (int e = 0; e < NE; e++) acc[e] += xv * w[e];
        }
        #pragma unroll
        for (int e = 0; e < NE; e++) {
            #pragma unroll
            for (int o = 16; o > 0; o >>= 1)
                acc[e] += __shfl_xor_sync(0xffffffffu, acc[e], o);
        }
        if (lane == 0) {
            float mx = acc[0];
            #pragma unroll
            for (int e = 1; e < NE; e++) mx = fmaxf(mx, acc[e]);
            float p[NE]; float s = 0.f;
            #pragma unroll
            for (int e = 0; e < NE; e++) { p[e] = expf(acc[e] - mx); s += p[e]; }
            float inv = 1.f / s;
            #pragma unroll
            for (int e = 0; e < NE; e++) p[e] *= inv;
            int i0 = 0;
            #pragma unroll
            for (int e = 1; e < NE; e++) if (p[e] > p[i0]) i0 = e;
            int i1 = (i0 == 0) ? 1 : 0;
            #pragma unroll
            for (int e = 0; e < NE; e++) if (e != i0 && p[e] > p[i1]) i1 = e;
            float w0 = p[i0], w1 = p[i1];
            float rn = 1.f / (w0 + w1);
            w0 *= rn; w1 *= rn;
            int pos0 = atomicAdd(&g_cnt[i0], 1);
            g_tok[i0 * TMAX + pos0]  = t;
            g_slot[i0 * TMAX + pos0] = t;
            g_wt[i0 * TMAX + pos0]   = w0;
            int pos1 = atomicAdd(&g_cnt[i1], 1);
            g_tok[i1 * TMAX + pos1]  = t;
            g_slot[i1 * TMAX + pos1] = T + t;
            g_wt[i1 * TMAX + pos1]   = w1;
            #pragma unroll
            for (int e = 0; e < NE; e++) atomicAdd(&s_p[e], p[e]);
        }
    }
    __syncthreads();
    if (threadIdx.x < NE) atomicAdd(&g_psum[threadIdx.x], s_p[threadIdx.x]);
}

// ------- merged gate+up GEMM + SwiGLU, 256 thr (2 CTAs/SM), tile 128x64 ------
__global__ __launch_bounds__(256, 2)
void k_gu_all(const __half* __restrict__ A_g, int T)
{
    const int z = blockIdx.z;
    int M, N, e = 0;
    bool gather;
    const __half *Bg, *Bu;
    __half* Ch;
    if (z == 0) {
        gather = false; M = T; N = DS;
        Bg = g_Wsg16; Bu = g_Wsu16;
        Ch = g_buf2H;
    } else {
        gather = true; e = z - 1;
        if (blockIdx.x >= DD / BN) return;
        M = g_cnt[e]; N = DD;
        size_t ws = (size_t)e * HD * DD;
        Bg = g_Wg16 + ws; Bu = g_Wu16 + ws;
        Ch = g_bufH + (size_t)e * TMAX * DD;
    }
    const int row0 = blockIdx.y * BM;
    if (row0 >= M) return;
    const int col0 = blockIdx.x * BN;
    const int K = HD;

    extern __shared__ char dsm[];
    const uint32_t sb = smem_u32(dsm);

    const int tid = threadIdx.x;
    const int wid = tid >> 5, lane = tid & 31;
    const int wm = wid & 3, wn = wid >> 2;     // 4x2 warp grid, 32x32 tiles
    const int g = lane >> 2, t4 = lane & 3;

    // A cp.async: 2 chunks/thread (128 rows x 4 chunks, 256 threads)
    size_t aoff; uint32_t adst;
    {
        int r = tid >> 1, c16 = (tid & 1) * 2;
        adst = r * (SA * 2) + c16 * 16;
        int gr = row0 + r;
        int grc = (gr < M) ? gr : (M - 1);
        if (gather) aoff = (size_t)g_tok[e * TMAX + grc] * K + c16 * 8;
        else        aoff = (size_t)grc * K + c16 * 8;
    }
    // B cp.async: 1 chunk/thread (32 rows x 8 chunks of 16B = 256)
    size_t boff; uint32_t bdst;
    {
        int br = tid >> 3, bc = tid & 7;
        bdst = br * (SB * 2) + bc * 16;
        boff = (size_t)br * N + col0 + bc * 8;
    }
    const size_t bstep = (size_t)BK * N;

    const int a_r = (lane & 7) + ((lane >> 3) & 1) * 8;
    const int a_c = ((lane >> 4) & 1) * 8;
    const uint32_t la = (uint32_t)(a_r * SA + a_c) * 2;
    const int b_k = (lane & 7) + ((lane >> 3) & 1) * 8;
    const int b_n = ((lane >> 4) & 1) * 8;
    const uint32_t lbT = (uint32_t)(b_k * SB + b_n) * 2;

    float accg[2][4][4], accu[2][4][4];
    #pragma unroll
    for (int mi = 0; mi < 2; mi++)
        #pragma unroll
        for (int ni = 0; ni < 4; ni++)
            #pragma unroll
            for (int q = 0; q < 4; q++) { accg[mi][ni][q] = 0.f; accu[mi][ni][q] = 0.f; }

    const int NC = K / BK;   // 32
    #pragma unroll
    for (int pc = 0; pc < 3; pc++) {
        uint32_t st = sb + pc * STG_GU;
        CP16(st + adst, A_g + aoff + (size_t)pc * BK);
        CP16(st + adst + 16, A_g + aoff + 8 + (size_t)pc * BK);
        CP16(st + TILE_A + bdst, Bg + boff + (size_t)pc * bstep);
        CP16(st + TILE_A + TILE_BB + bdst, Bu + boff + (size_t)pc * bstep);
        CPCOMMIT();
    }

    int s_next = 3;
    for (int c = 0; c < NC; c++) {
        CPWAIT2();
        __syncthreads();
        {
            int nc3 = (c + 3 < NC) ? c + 3 : NC - 1;
            uint32_t st = sb + s_next * STG_GU;
            CP16(st + adst, A_g + aoff + (size_t)nc3 * BK);
            CP16(st + adst + 16, A_g + aoff + 8 + (size_t)nc3 * BK);
            CP16(st + TILE_A + bdst, Bg + boff + (size_t)nc3 * bstep);
            CP16(st + TILE_A + TILE_BB + bdst, Bu + boff + (size_t)nc3 * bstep);
            CPCOMMIT();
        }
        s_next = (s_next + 1) & 3;
        const uint32_t st = sb + (c & 3) * STG_GU;
        #pragma unroll
        for (int ks = 0; ks < 2; ks++) {
            uint32_t fA[2][4], fBg[2][4], fBu[2][4];
            #pragma unroll
            for (int mi = 0; mi < 2; mi++) {
                uint32_t ro = (uint32_t)((wm * 32 + mi * 16) * SA * 2) + ks * 32;
                ldsm4(fA[mi], st + ro + la);
            }
            #pragma unroll
            for (int nb = 0; nb < 2; nb++) {
                uint32_t bo = (uint32_t)(ks * 16 * SB * 2) + (uint32_t)((wn * 32 + nb * 16) * 2);
                ldsm4t(fBg[nb], st + TILE_A + bo + lbT);
                ldsm4t(fBu[nb], st + TILE_A + TILE_BB + bo + lbT);
            }
            #pragma unroll
            for (int mi = 0; mi < 2; mi++)
                #pragma unroll
                for (int ni = 0; ni < 4; ni++)
                    mma_f16(accg[mi][ni], fA[mi], &fBg[ni >> 1][(ni & 1) * 2]);
            #pragma unroll
            for (int mi = 0; mi < 2; mi++)
                #pragma unroll
                for (int ni = 0; ni < 4; ni++)
                    mma_f16(accu[mi][ni], fA[mi], &fBu[ni >> 1][(ni & 1) * 2]);
        }
    }

    // epilogue: swiglu (weighted if gather), single-fp16 store
    #pragma unroll
    for (int mi = 0; mi < 2; mi++) {
        int p0 = row0 + wm * 32 + mi * 16 + g;
        #pragma unroll
        for (int half = 0; half < 2; half++) {
            int p = p0 + half * 8;
            if (p >= M) continue;
            float w = gather ? g_wt[e * TMAX + p] : 1.f;
            size_t rowo = (size_t)p * N;
            #pragma unroll
            for (int ni = 0; ni < 4; ni++) {
                int col = col0 + wn * 32 + ni * 8 + 2 * t4;
                float gv0 = accg[mi][ni][half * 2 + 0];
                float gv1 = accg[mi][ni][half * 2 + 1];
                float uv0 = accu[mi][ni][half * 2 + 0];
                float uv1 = accu[mi][ni][half * 2 + 1];
                float v0 = w * (gv0 / (1.f + expf(-gv0))) * uv0;
                float v1 = w * (gv1 / (1.f + expf(-gv1))) * uv1;
                *(__half2*)(Ch + rowo + col) = __floats2half2_rn(v0, v1);
            }
        }
    }
}

// ------- merged down GEMM, 256 thr (2 CTAs/SM), tile 128x64 ------------------
__global__ __launch_bounds__(256, 2)
void k_dn_all(float* __restrict__ out, int T)
{
    const int z = blockIdx.z;
    int M, K, e = 0;
    bool scatter;
    const __half *A_g, *B;
    if (z == 0) {
        scatter = false; M = T; K = DS;
        A_g = g_buf2H;
        B = g_Wsd16;
    } else {
        scatter = true; e = z - 1;
        M = g_cnt[e]; K = DD;
        A_g = g_bufH + (size_t)e * TMAX * DD;
        B = g_Wd16 + (size_t)e * DD * HD;
    }
    const int row0 = blockIdx.y * BM;
    if (row0 >= M) return;
    const int col0 = blockIdx.x * BN;
    const int N = HD;

    extern __shared__ char dsm[];
    const uint32_t sb = smem_u32(dsm);

    const int tid = threadIdx.x;
    const int wid = tid >> 5, lane = tid & 31;
    const int wm = wid & 3, wn = wid >> 2;
    const int g = lane >> 2, t4 = lane & 3;

    size_t aoff; uint32_t adst;
    {
        int r = tid >> 1, c16 = (tid & 1) * 2;
        adst = r * (SA * 2) + c16 * 16;
        int gr = row0 + r;
        int grc = (gr < M) ? gr : (M - 1);
        aoff = (size_t)grc * K + c16 * 8;
    }
    size_t boff; uint32_t bdst;
    {
        int br = tid >> 3, bc = tid & 7;
        bdst = br * (SB * 2) + bc * 16;
        boff = (size_t)br * N + col0 + bc * 8;
    }
    const size_t bstep = (size_t)BK * N;

    const int a_r = (lane & 7) + ((lane >> 3) & 1) * 8;
    const int a_c = ((lane >> 4) & 1) * 8;
    const uint32_t la = (uint32_t)(a_r * SA + a_c) * 2;
    const int b_k = (lane & 7) + ((lane >> 3) & 1) * 8;
    const int b_n = ((lane >> 4) & 1) * 8;
    const uint32_t lbT = (uint32_t)(b_k * SB + b_n) * 2;

    float acc[2][4][4];
    #pragma unroll
    for (int mi = 0; mi < 2; mi++)
        #pragma unroll
        for (int ni = 0; ni < 4; ni++)
            #pragma unroll
            for (int q = 0; q < 4; q++) acc[mi][ni][q] = 0.f;

    const int NC = K / BK;
    #pragma unroll
    for (int pc = 0; pc < 3; pc++) {
        uint32_t st = sb + pc * STG_DN;
        CP16(st + adst, A_g + aoff + (size_t)pc * BK);
        CP16(st + adst + 16, A_g + aoff + 8 + (size_t)pc * BK);
        CP16(st + TILE_A + bdst, B + boff + (size_t)pc * bstep);
        CPCOMMIT();
    }

    int s_next = 3;
    for (int c = 0; c < NC; c++) {
        CPWAIT2();
        __syncthreads();
        {
            int nc3 = (c + 3 < NC) ? c + 3 : NC - 1;
            uint32_t st = sb + s_next * STG_DN;
            CP16(st + adst, A_g + aoff + (size_t)nc3 * BK);
            CP16(st + adst + 16, A_g + aoff + 8 + (size_t)nc3 * BK);
            CP16(st + TILE_A + bdst, B + boff + (size_t)nc3 * bstep);
            CPCOMMIT();
        }
        s_next = (s_next + 1) & 3;
        const uint32_t st = sb + (c & 3) * STG_DN;
        #pragma unroll
        for (int ks = 0; ks < 2; ks++) {
            uint32_t fA[2][4], fB[2][4];
            #pragma unroll
            for (int mi = 0; mi < 2; mi++) {
                uint32_t ro = (uint32_t)((wm * 32 + mi * 16) * SA * 2) + ks * 32;
                ldsm4(fA[mi], st + ro + la);
            }
            #pragma unroll
            for (int nb = 0; nb < 2; nb++) {
                uint32_t bo = (uint32_t)(ks * 16 * SB * 2) + (uint32_t)((wn * 32 + nb * 16) * 2);
                ldsm4t(fB[nb], st + TILE_A + bo + lbT);
            }
            #pragma unroll
            for (int mi = 0; mi < 2; mi++)
                #pragma unroll
                for (int ni = 0; ni < 4; ni++)
                    mma_f16(acc[mi][ni], fA[mi], &fB[ni >> 1][(ni & 1) * 2]);
        }
    }

    #pragma unroll
    for (int mi = 0; mi < 2; mi++) {
        int p0 = row0 + wm * 32 + mi * 16 + g;
        int p1 = p0 + 8;
        if (scatter) {
            __half* c0 = (p0 < M) ? g_routed + (size_t)g_slot[e * TMAX + p0] * HD : nullptr;
            __half* c1 = (p1 < M) ? g_routed + (size_t)g_slot[e * TMAX + p1] * HD : nullptr;
            #pragma unroll
            for (int ni = 0; ni < 4; ni++) {
                int col = col0 + wn * 32 + ni * 8 + 2 * t4;
                if (c0) *(__half2*)(c0 + col) = __floats2half2_rn(acc[mi][ni][0], acc[mi][ni][1]);
                if (c1) *(__half2*)(c1 + col) = __floats2half2_rn(acc[mi][ni][2], acc[mi][ni][3]);
            }
        } else {
            float* c0 = out + (size_t)p0 * HD;
            float* c1 = out + (size_t)p1 * HD;
            #pragma unroll
            for (int ni = 0; ni < 4; ni++) {
                int col = col0 + wn * 32 + ni * 8 + 2 * t4;
                *(float2*)(c0 + col) = make_float2(acc[mi][ni][0], acc[mi][ni][1]);
                *(float2*)(c1 + col) = make_float2(acc[mi][ni][2], acc[mi][ni][3]);
            }
        }
    }
}

// ---------------- final: out += routed slots (fp16); aux loss tail -----------
__global__ void k_final(float* __restrict__ out, int n4, int T, int out_size) {
    if (blockIdx.x == 0 && threadIdx.x == 0) {
        float a = 0.f;
        for (int e = 0; e < NE; e++) { float m = g_psum[e] / (float)T; a += m * m; }
        a *= (float)NE;
        for (size_t i = (size_t)T * HD; i < (size_t)out_size; i++) out[i] = a;
    }
    const uint2* r = (const uint2*)g_routed;
    float4* o4 = (float4*)out;
    int i = blockIdx.x * blockDim.x + threadIdx.x;
    int stride = gridDim.x * blockDim.x;
    for (; i < n4; i += stride) {
        float4 a = o4[i];
        uint2 b2 = r[i], c2 = r[i + n4];
        __half2 b01 = *(__half2*)&b2.x, b23 = *(__half2*)&b2.y;
        __half2 c01 = *(__half2*)&c2.x, c23 = *(__half2*)&c2.y;
        float2 fb01 = __half22float2(b01), fb23 = __half22float2(b23);
        float2 fc01 = __half22float2(c01), fc23 = __half22float2(c23);
        a.x += fb01.x + fc01.x;
        a.y += fb01.y + fc01.y;
        a.z += fb23.x + fc23.x;
        a.w += fb23.y + fc23.y;
        o4[i] = a;
    }
}

// ---------------- launch -----------------------------------------------------
extern "C" void kernel_launch(void* const* d_in, const int* in_sizes, int n_in,
                              void* d_out, int out_size) {
    const float* x   = (const float*)d_in[0];
    const float* Wr  = (const float*)d_in[1];
    const float* Wg  = (const float*)d_in[2];
    const float* Wu  = (const float*)d_in[3];
    const float* Wd  = (const float*)d_in[4];
    const float* Wsg = (const float*)d_in[5];
    const float* Wsu = (const float*)d_in[6];
    const float* Wsd = (const float*)d_in[7];
    float* out = (float*)d_out;
    const int T = in_sizes[0] / HD;   // 8192

    __half* xh;
    cudaGetSymbolAddress((void**)&xh, g_xh);

    cudaFuncSetAttribute(k_gu_all, cudaFuncAttributeMaxDynamicSharedMemorySize, SMEM_GU);
    cudaFuncSetAttribute(k_dn_all, cudaFuncAttributeMaxDynamicSharedMemorySize, SMEM_DN);

    // 0: fused prep — x->fp16 (+zero counters) and all weight converts
    k_prep<<<dim3(512, 1, 7), 256>>>(x, T * HD / 4, Wsg, Wsu, Wsd, Wg, Wu, Wd);
    // 1: router
    k_router<<<T / 8, 256>>>(x, Wr, T);
    // 2: merged gate+up (+swiglu), 128x64 tiles, 2 CTAs/SM
    k_gu_all<<<dim3(DS / BN, T / BM, NE + 1), 256, SMEM_GU>>>(xh, T);
    // 3: merged down, 128x64 tiles, 2 CTAs/SM
    k_dn_all<<<dim3(HD / BN, T / BM, NE + 1), 256, SMEM_DN>>>(out, T);
    // 4: combine + aux loss
    k_final<<<2048, 256>>>(out, (T * HD) / 4, T, out_size);
}

// round 15
// speedup vs baseline: 1.0681x; 1.0681x over previous
#include <cuda_runtime.h>
#include <cuda_fp16.h>
#include <math.h>
#include <stdint.h>

#define NE   8
#define HD   1024
#define DD   512
#define DS   1024
#define TMAX 8192

#define BM 128
#define BN 128
#define BK 32
#define SA 40                    // A: 16-bit elems per row (32 + 8 pad)
#define SB 136                   // B: 16-bit elems per row (128 + 8 pad)
#define TILE_A (128 * SA * 2)    // 10240 B
#define TILE_BB (32 * SB * 2)    // 8704 B
#define STG_GU (TILE_A + 2 * TILE_BB)   // A, Bg, Bu = 27648
#define STG_DN (TILE_A + TILE_BB)       // A, B = 18944
#define SMEM_GU (4 * STG_GU)     // 110592
#define SMEM_DN (4 * STG_DN)     // 75776

// ---------------- scratch (static device globals; no allocations) ------------
__device__ __align__(16) __half g_xh[(size_t)TMAX * HD];
__device__ __align__(16) __half g_bufH[(size_t)NE * TMAX * DD];   // routed gu out
__device__ __align__(16) __half g_buf2H[(size_t)TMAX * DS];       // shared gu out
__device__ __align__(16) __half g_routed[(size_t)2 * TMAX * HD];  // fp16 slots
// fp16 weights in NATURAL [K][N] layout
__device__ __align__(16) __half g_Wsg16[(size_t)HD * DS];
__device__ __align__(16) __half g_Wsu16[(size_t)HD * DS];
__device__ __align__(16) __half g_Wsd16[(size_t)DS * HD];
__device__ __align__(16) __half g_Wg16[(size_t)NE * HD * DD];
__device__ __align__(16) __half g_Wu16[(size_t)NE * HD * DD];
__device__ __align__(16) __half g_Wd16[(size_t)NE * DD * HD];
__device__ int   g_cnt[NE];
__device__ int   g_tok[NE * TMAX];
__device__ int   g_slot[NE * TMAX];
__device__ float g_wt[NE * TMAX];
__device__ float g_psum[NE];

// ---------------- asm helpers ------------------------------------------------
__device__ __forceinline__ uint32_t smem_u32(const void* p) {
    uint32_t a;
    asm("{ .reg .u64 t; cvta.to.shared.u64 t, %1; cvt.u32.u64 %0, t; }" : "=r"(a) : "l"(p));
    return a;
}
#define CP16(dst, src) \
    asm volatile("cp.async.cg.shared.global [%0], [%1], 16;" :: "r"(dst), "l"(src) : "memory")
#define CPCOMMIT() asm volatile("cp.async.commit_group;" ::: "memory")
#define CPWAIT2()  asm volatile("cp.async.wait_group 2;" ::: "memory")

__device__ __forceinline__ void ldsm4(uint32_t* r, uint32_t addr) {
    asm volatile("ldmatrix.sync.aligned.m8n8.x4.shared.b16 {%0,%1,%2,%3}, [%4];"
        : "=r"(r[0]), "=r"(r[1]), "=r"(r[2]), "=r"(r[3]) : "r"(addr));
}
__device__ __forceinline__ void ldsm4t(uint32_t* r, uint32_t addr) {
    asm volatile("ldmatrix.sync.aligned.m8n8.x4.trans.shared.b16 {%0,%1,%2,%3}, [%4];"
        : "=r"(r[0]), "=r"(r[1]), "=r"(r[2]), "=r"(r[3]) : "r"(addr));
}
__device__ __forceinline__ void mma_f16(float* c, const uint32_t* a, const uint32_t* b) {
    asm volatile(
        "mma.sync.aligned.m16n8k16.row.col.f32.f16.f16.f32 "
        "{%0,%1,%2,%3}, {%4,%5,%6,%7}, {%8,%9}, {%0,%1,%2,%3};\n"
        : "+f"(c[0]), "+f"(c[1]), "+f"(c[2]), "+f"(c[3])
        : "r"(a[0]), "r"(a[1]), "r"(a[2]), "r"(a[3]), "r"(b[0]), "r"(b[1]));
}

// ---------------- init: zero routing counters (must precede prep) ------------
__global__ void k_init() {
    if (threadIdx.x < NE) { g_cnt[threadIdx.x] = 0; g_psum[threadIdx.x] = 0.f; }
}

// ---- fused prep: z=0 x->fp16; z=1..6 weight conv; z=7 ROUTER ----------------
__global__ void k_prep(const float* __restrict__ x, int xn4,
                       const float* __restrict__ Wsg, const float* __restrict__ Wsu,
                       const float* __restrict__ Wsd, const float* __restrict__ Wg,
                       const float* __restrict__ Wu,  const float* __restrict__ Wd,
                       const float* __restrict__ Wr, int T) {
    const int z = blockIdx.z;
    if (z == 7) {
        // ---- router: 8 warps/block, one token per warp ----
        __shared__ float s_p[NE];
        if (threadIdx.x < NE) s_p[threadIdx.x] = 0.f;
        __syncthreads();
        int warp = blockIdx.x * 8 + (threadIdx.x >> 5);
        int lane = threadIdx.x & 31;
        if (warp < T) {
            int t = warp;
            const float* xr = x + (size_t)t * HD;
            float acc[NE];
            #pragma unroll
            for (int e = 0; e < NE; e++) acc[e] = 0.f;
            for (int i = lane; i < HD; i += 32) {
                float xv = xr[i];
                const float* w = Wr + (size_t)i * NE;
                #pragma unroll
                for (int e = 0; e < NE; e++) acc[e] += xv * w[e];
            }
            #pragma unroll
            for (int e = 0; e < NE; e++) {
                #pragma unroll
                for (int o = 16; o > 0; o >>= 1)
                    acc[e] += __shfl_xor_sync(0xffffffffu, acc[e], o);
            }
            if (lane == 0) {
                float mx = acc[0];
                #pragma unroll
                for (int e = 1; e < NE; e++) mx = fmaxf(mx, acc[e]);
                float p[NE]; float s = 0.f;
                #pragma unroll
                for (int e = 0; e < NE; e++) { p[e] = expf(acc[e] - mx); s += p[e]; }
                float inv = 1.f / s;
                #pragma unroll
                for (int e = 0; e < NE; e++) p[e] *= inv;
                int i0 = 0;
                #pragma unroll
                for (int e = 1; e < NE; e++) if (p[e] > p[i0]) i0 = e;
                int i1 = (i0 == 0) ? 1 : 0;
                #pragma unroll
                for (int e = 0; e < NE; e++) if (e != i0 && p[e] > p[i1]) i1 = e;
                float w0 = p[i0], w1 = p[i1];
                float rn = 1.f / (w0 + w1);
                w0 *= rn; w1 *= rn;
                int pos0 = atomicAdd(&g_cnt[i0], 1);
                g_tok[i0 * TMAX + pos0]  = t;
                g_slot[i0 * TMAX + pos0] = t;
                g_wt[i0 * TMAX + pos0]   = w0;
                int pos1 = atomicAdd(&g_cnt[i1], 1);
                g_tok[i1 * TMAX + pos1]  = t;
                g_slot[i1 * TMAX + pos1] = T + t;
                g_wt[i1 * TMAX + pos1]   = w1;
                #pragma unroll
                for (int e = 0; e < NE; e++) atomicAdd(&s_p[e], p[e]);
            }
        }
        __syncthreads();
        if (threadIdx.x < NE) atomicAdd(&g_psum[threadIdx.x], s_p[threadIdx.x]);
        return;
    }
    const float* in; __half* o; size_t n4;
    if (z == 0)      { in = x;   o = g_xh;    n4 = (size_t)xn4; }
    else if (z == 1) { in = Wsg; o = g_Wsg16; n4 = (size_t)HD * DS / 4; }
    else if (z == 2) { in = Wsu; o = g_Wsu16; n4 = (size_t)HD * DS / 4; }
    else if (z == 3) { in = Wsd; o = g_Wsd16; n4 = (size_t)DS * HD / 4; }
    else if (z == 4) { in = Wg;  o = g_Wg16;  n4 = (size_t)NE * HD * DD / 4; }
    else if (z == 5) { in = Wu;  o = g_Wu16;  n4 = (size_t)NE * HD * DD / 4; }
    else             { in = Wd;  o = g_Wd16;  n4 = (size_t)NE * DD * HD / 4; }
    size_t i = (size_t)blockIdx.x * blockDim.x + threadIdx.x;
    size_t stride = (size_t)gridDim.x * blockDim.x;
    for (; i < n4; i += stride) {
        float4 v = ((const float4*)in)[i];
        __half2 h01 = __floats2half2_rn(v.x, v.y);
        __half2 h23 = __floats2half2_rn(v.z, v.w);
        ((uint2*)o)[i] = make_uint2(*(uint32_t*)&h01, *(uint32_t*)&h23);
    }
}

// ------- merged gate+up GEMM + SwiGLU, 512 thr, tile 128x128 (R13 config) ----
__global__ __launch_bounds__(512, 1)
void k_gu_all(const __half* __restrict__ A_g, int T)
{
    const int z = blockIdx.z;
    int M, N, e = 0;
    bool gather;
    const __half *Bg, *Bu;
    __half* Ch;
    if (z == 0) {
        gather = false; M = T; N = DS;
        Bg = g_Wsg16; Bu = g_Wsu16;
        Ch = g_buf2H;
    } else {
        gather = true; e = z - 1;
        if (blockIdx.x >= DD / BN) return;
        M = g_cnt[e]; N = DD;
        size_t ws = (size_t)e * HD * DD;
        Bg = g_Wg16 + ws; Bu = g_Wu16 + ws;
        Ch = g_bufH + (size_t)e * TMAX * DD;
    }
    const int row0 = blockIdx.y * BM;
    if (row0 >= M) return;
    const int col0 = blockIdx.x * BN;
    const int K = HD;

    extern __shared__ char dsm[];
    const uint32_t sb = smem_u32(dsm);

    const int tid = threadIdx.x;
    const int wid = tid >> 5, lane = tid & 31;
    const int wm = wid & 3, wn = wid >> 2;
    const int g = lane >> 2, t4 = lane & 3;
    const int kswap = wid & 1;

    size_t aoff; uint32_t adst;
    {
        int r = tid >> 2, c16 = tid & 3;
        adst = r * (SA * 2) + c16 * 16;
        int gr = row0 + r;
        int grc = (gr < M) ? gr : (M - 1);
        if (gather) aoff = (size_t)g_tok[e * TMAX + grc] * K + c16 * 8;
        else        aoff = (size_t)grc * K + c16 * 8;
    }
    size_t boff; uint32_t bdst;
    {
        int br = tid >> 4, bc = tid & 15;
        bdst = br * (SB * 2) + bc * 16;
        boff = (size_t)br * N + col0 + bc * 8;
    }
    const size_t bstep = (size_t)BK * N;

    const int a_r = (lane & 7) + ((lane >> 3) & 1) * 8;
    const int a_c = ((lane >> 4) & 1) * 8;
    const uint32_t la = (uint32_t)(a_r * SA + a_c) * 2;
    const int b_k = (lane & 7) + ((lane >> 3) & 1) * 8;
    const int b_n = ((lane >> 4) & 1) * 8;
    const uint32_t lbT = (uint32_t)(b_k * SB + b_n) * 2;

    float accg[2][4][4], accu[2][4][4];
    #pragma unroll
    for (int mi = 0; mi < 2; mi++)
        #pragma unroll
        for (int ni = 0; ni < 4; ni++)
            #pragma unroll
            for (int q = 0; q < 4; q++) { accg[mi][ni][q] = 0.f; accu[mi][ni][q] = 0.f; }

    const int NC = K / BK;   // 32
    #pragma unroll
    for (int pc = 0; pc < 3; pc++) {
        uint32_t st = sb + pc * STG_GU;
        CP16(st + adst, A_g + aoff + (size_t)pc * BK);
        CP16(st + TILE_A + bdst, Bg + boff + (size_t)pc * bstep);
        CP16(st + TILE_A + TILE_BB + bdst, Bu + boff + (size_t)pc * bstep);
        CPCOMMIT();
    }

    int s_next = 3;
    for (int c = 0; c < NC; c++) {
        CPWAIT2();
        __syncthreads();
        {
            int nc3 = (c + 3 < NC) ? c + 3 : NC - 1;
            uint32_t st = sb + s_next * STG_GU;
            CP16(st + adst, A_g + aoff + (size_t)nc3 * BK);
            CP16(st + TILE_A + bdst, Bg + boff + (size_t)nc3 * bstep);
            CP16(st + TILE_A + TILE_BB + bdst, Bu + boff + (size_t)nc3 * bstep);
            CPCOMMIT();
        }
        s_next = (s_next + 1) & 3;
        const uint32_t st = sb + (c & 3) * STG_GU;
        #pragma unroll
        for (int kss = 0; kss < 2; kss++) {
            const int ks = kswap ? (1 - kss) : kss;
            uint32_t fA[2][4], fBg[2][4], fBu[2][4];
            #pragma unroll
            for (int mi = 0; mi < 2; mi++) {
                uint32_t ro = (uint32_t)((wm * 32 + mi * 16) * SA * 2) + ks * 32;
                ldsm4(fA[mi], st + ro + la);
            }
            #pragma unroll
            for (int nb = 0; nb < 2; nb++) {
                uint32_t bo = (uint32_t)(ks * 16 * SB * 2) + (uint32_t)((wn * 32 + nb * 16) * 2);
                ldsm4t(fBg[nb], st + TILE_A + bo + lbT);
                ldsm4t(fBu[nb], st + TILE_A + TILE_BB + bo + lbT);
            }
            #pragma unroll
            for (int mi = 0; mi < 2; mi++)
                #pragma unroll
                for (int ni = 0; ni < 4; ni++)
                    mma_f16(accg[mi][ni], fA[mi], &fBg[ni >> 1][(ni & 1) * 2]);
            #pragma unroll
            for (int mi = 0; mi < 2; mi++)
                #pragma unroll
                for (int ni = 0; ni < 4; ni++)
                    mma_f16(accu[mi][ni], fA[mi], &fBu[ni >> 1][(ni & 1) * 2]);
        }
    }

    // epilogue: swiglu (weighted if gather), single-fp16 store
    #pragma unroll
    for (int mi = 0; mi < 2; mi++) {
        int p0 = row0 + wm * 32 + mi * 16 + g;
        #pragma unroll
        for (int half = 0; half < 2; half++) {
            int p = p0 + half * 8;
            if (p >= M) continue;
            float w = gather ? g_wt[e * TMAX + p] : 1.f;
            size_t rowo = (size_t)p * N;
            #pragma unroll
            for (int ni = 0; ni < 4; ni++) {
                int col = col0 + wn * 32 + ni * 8 + 2 * t4;
                float gv0 = accg[mi][ni][half * 2 + 0];
                float gv1 = accg[mi][ni][half * 2 + 1];
                float uv0 = accu[mi][ni][half * 2 + 0];
                float uv1 = accu[mi][ni][half * 2 + 1];
                float v0 = w * (gv0 / (1.f + expf(-gv0))) * uv0;
                float v1 = w * (gv1 / (1.f + expf(-gv1))) * uv1;
                *(__half2*)(Ch + rowo + col) = __floats2half2_rn(v0, v1);
            }
        }
    }
}

// ------- merged down GEMM, 512 thr, tile 128x128 (R13 config) ----------------
__global__ __launch_bounds__(512, 1)
void k_dn_all(float* __restrict__ out, int T)
{
    const int z = blockIdx.z;
    int M, K, e = 0;
    bool scatter;
    const __half *A_g, *B;
    if (z == 0) {
        scatter = false; M = T; K = DS;
        A_g = g_buf2H;
        B = g_Wsd16;
    } else {
        scatter = true; e = z - 1;
        M = g_cnt[e]; K = DD;
        A_g = g_bufH + (size_t)e * TMAX * DD;
        B = g_Wd16 + (size_t)e * DD * HD;
    }
    const int row0 = blockIdx.y * BM;
    if (row0 >= M) return;
    const int col0 = blockIdx.x * BN;
    const int N = HD;

    extern __shared__ char dsm[];
    const uint32_t sb = smem_u32(dsm);

    const int tid = threadIdx.x;
    const int wid = tid >> 5, lane = tid & 31;
    const int wm = wid & 3, wn = wid >> 2;
    const int g = lane >> 2, t4 = lane & 3;
    const int kswap = wid & 1;

    size_t aoff; uint32_t adst;
    {
        int r = tid >> 2, c16 = tid & 3;
        adst = r * (SA * 2) + c16 * 16;
        int gr = row0 + r;
        int grc = (gr < M) ? gr : (M - 1);
        aoff = (size_t)grc * K + c16 * 8;
    }
    size_t boff; uint32_t bdst;
    {
        int br = tid >> 4, bc = tid & 15;
        bdst = br * (SB * 2) + bc * 16;
        boff = (size_t)br * N + col0 + bc * 8;
    }
    const size_t bstep = (size_t)BK * N;

    const int a_r = (lane & 7) + ((lane >> 3) & 1) * 8;
    const int a_c = ((lane >> 4) & 1) * 8;
    const uint32_t la = (uint32_t)(a_r * SA + a_c) * 2;
    const int b_k = (lane & 7) + ((lane >> 3) & 1) * 8;
    const int b_n = ((lane >> 4) & 1) * 8;
    const uint32_t lbT = (uint32_t)(b_k * SB + b_n) * 2;

    float acc[2][4][4];
    #pragma unroll
    for (int mi = 0; mi < 2; mi++)
        #pragma unroll
        for (int ni = 0; ni < 4; ni++)
            #pragma unroll
            for (int q = 0; q < 4; q++) acc[mi][ni][q] = 0.f;

    const int NC = K / BK;
    #pragma unroll
    for (int pc = 0; pc < 3; pc++) {
        uint32_t st = sb + pc * STG_DN;
        CP16(st + adst, A_g + aoff + (size_t)pc * BK);
        CP16(st + TILE_A + bdst, B + boff + (size_t)pc * bstep);
        CPCOMMIT();
    }

    int s_next = 3;
    for (int c = 0; c < NC; c++) {
        CPWAIT2();
        __syncthreads();
        {
            int nc3 = (c + 3 < NC) ? c + 3 : NC - 1;
            uint32_t st = sb + s_next * STG_DN;
            CP16(st + adst, A_g + aoff + (size_t)nc3 * BK);
            CP16(st + TILE_A + bdst, B + boff + (size_t)nc3 * bstep);
            CPCOMMIT();
        }
        s_next = (s_next + 1) & 3;
        const uint32_t st = sb + (c & 3) * STG_DN;
        #pragma unroll
        for (int kss = 0; kss < 2; kss++) {
            const int ks = kswap ? (1 - kss) : kss;
            uint32_t fA[2][4], fB[2][4];
            #pragma unroll
            for (int mi = 0; mi < 2; mi++) {
                uint32_t ro = (uint32_t)((wm * 32 + mi * 16) * SA * 2) + ks * 32;
                ldsm4(fA[mi], st + ro + la);
            }
            #pragma unroll
            for (int nb = 0; nb < 2; nb++) {
                uint32_t bo = (uint32_t)(ks * 16 * SB * 2) + (uint32_t)((wn * 32 + nb * 16) * 2);
                ldsm4t(fB[nb], st + TILE_A + bo + lbT);
            }
            #pragma unroll
            for (int mi = 0; mi < 2; mi++)
                #pragma unroll
                for (int ni = 0; ni < 4; ni++)
                    mma_f16(acc[mi][ni], fA[mi], &fB[ni >> 1][(ni & 1) * 2]);
        }
    }

    #pragma unroll
    for (int mi = 0; mi < 2; mi++) {
        int p0 = row0 + wm * 32 + mi * 16 + g;
        int p1 = p0 + 8;
        if (scatter) {
            __half* c0 = (p0 < M) ? g_routed + (size_t)g_slot[e * TMAX + p0] * HD : nullptr;
            __half* c1 = (p1 < M) ? g_routed + (size_t)g_slot[e * TMAX + p1] * HD : nullptr;
            #pragma unroll
            for (int ni = 0; ni < 4; ni++) {
                int col = col0 + wn * 32 + ni * 8 + 2 * t4;
                if (c0) *(__half2*)(c0 + col) = __floats2half2_rn(acc[mi][ni][0], acc[mi][ni][1]);
                if (c1) *(__half2*)(c1 + col) = __floats2half2_rn(acc[mi][ni][2], acc[mi][ni][3]);
            }
        } else {
            float* c0 = out + (size_t)p0 * HD;
            float* c1 = out + (size_t)p1 * HD;
            #pragma unroll
            for (int ni = 0; ni < 4; ni++) {
                int col = col0 + wn * 32 + ni * 8 + 2 * t4;
                *(float2*)(c0 + col) = make_float2(acc[mi][ni][0], acc[mi][ni][1]);
                *(float2*)(c1 + col) = make_float2(acc[mi][ni][2], acc[mi][ni][3]);
            }
        }
    }
}

// ---------------- final: out += routed slots (fp16); aux loss tail -----------
__global__ void k_final(float* __restrict__ out, int n4, int T, int out_size) {
    if (blockIdx.x == 0 && threadIdx.x == 0) {
        float a = 0.f;
        for (int e = 0; e < NE; e++) { float m = g_psum[e] / (float)T; a += m * m; }
        a *= (float)NE;
        for (size_t i = (size_t)T * HD; i < (size_t)out_size; i++) out[i] = a;
    }
    const uint2* r = (const uint2*)g_routed;
    float4* o4 = (float4*)out;
    int i = blockIdx.x * blockDim.x + threadIdx.x;
    int stride = gridDim.x * blockDim.x;
    for (; i < n4; i += stride) {
        float4 a = o4[i];
        uint2 b2 = r[i], c2 = r[i + n4];
        __half2 b01 = *(__half2*)&b2.x, b23 = *(__half2*)&b2.y;
        __half2 c01 = *(__half2*)&c2.x, c23 = *(__half2*)&c2.y;
        float2 fb01 = __half22float2(b01), fb23 = __half22float2(b23);
        float2 fc01 = __half22float2(c01), fc23 = __half22float2(c23);
        a.x += fb01.x + fc01.x;
        a.y += fb01.y + fc01.y;
        a.z += fb23.x + fc23.x;
        a.w += fb23.y + fc23.y;
        o4[i] = a;
    }
}

// ---------------- launch -----------------------------------------------------
extern "C" void kernel_launch(void* const* d_in, const int* in_sizes, int n_in,
                              void* d_out, int out_size) {
    const float* x   = (const float*)d_in[0];
    const float* Wr  = (const float*)d_in[1];
    const float* Wg  = (const float*)d_in[2];
    const float* Wu  = (const float*)d_in[3];
    const float* Wd  = (const float*)d_in[4];
    const float* Wsg = (const float*)d_in[5];
    const float* Wsu = (const float*)d_in[6];
    const float* Wsd = (const float*)d_in[7];
    float* out = (float*)d_out;
    const int T = in_sizes[0] / HD;   // 8192

    __half* xh;
    cudaGetSymbolAddress((void**)&xh, g_xh);

    cudaFuncSetAttribute(k_gu_all, cudaFuncAttributeMaxDynamicSharedMemorySize, SMEM_GU);
    cudaFuncSetAttribute(k_dn_all, cudaFuncAttributeMaxDynamicSharedMemorySize, SMEM_DN);

    // 0: zero routing counters (ordered before router atomics)
    k_init<<<1, 32>>>();
    // 1: fused prep — conversions (z=0..6) + router (z=7) in one launch
    k_prep<<<dim3(1024, 1, 8), 256>>>(x, T * HD / 4, Wsg, Wsu, Wsd, Wg, Wu, Wd, Wr, T);
    // 2: merged gate+up (+swiglu)
    k_gu_all<<<dim3(DS / BN, T / BM, NE + 1), 512, SMEM_GU>>>(xh, T);
    // 3: merged down
    k_dn_all<<<dim3(HD / BN, T / BM, NE + 1), 512, SMEM_DN>>>(out, T);
    // 4: combine + aux loss
    k_final<<<2048, 256>>>(out, (T * HD) / 4, T, out_size);
}

// round 16
// speedup vs baseline: 1.0862x; 1.0170x over previous
#include <cuda_runtime.h>
#include <cuda_fp16.h>
#include <math.h>
#include <stdint.h>

#define NE   8
#define HD   1024
#define DD   512
#define DS   1024
#define TMAX 8192

#define BM 128
#define BN 128
#define BK 32
#define SA 40                    // A: 16-bit elems per row (32 + 8 pad)
#define SB 136                   // B: 16-bit elems per row (128 + 8 pad)
#define TILE_A (128 * SA * 2)    // 10240 B
#define TILE_BB (32 * SB * 2)    // 8704 B
#define STG_GU (TILE_A + 2 * TILE_BB)   // A, Bg, Bu = 27648
#define STG_DN (TILE_A + TILE_BB)       // A, B = 18944
#define SMEM_GU (4 * STG_GU)     // 110592
#define SMEM_DN (4 * STG_DN)     // 75776

// ---------------- scratch (static device globals; no allocations) ------------
__device__ __align__(16) __half g_xh[(size_t)TMAX * HD];
__device__ __align__(16) __half g_bufH[(size_t)NE * TMAX * DD];   // routed gu out
__device__ __align__(16) __half g_buf2H[(size_t)TMAX * DS];       // shared gu out
__device__ __align__(16) __half g_routed[(size_t)2 * TMAX * HD];  // fp16 slots
// fp16 weights in NATURAL [K][N] layout
__device__ __align__(16) __half g_Wsg16[(size_t)HD * DS];
__device__ __align__(16) __half g_Wsu16[(size_t)HD * DS];
__device__ __align__(16) __half g_Wsd16[(size_t)DS * HD];
__device__ __align__(16) __half g_Wg16[(size_t)NE * HD * DD];
__device__ __align__(16) __half g_Wu16[(size_t)NE * HD * DD];
__device__ __align__(16) __half g_Wd16[(size_t)NE * DD * HD];
__device__ int   g_cnt[NE];
__device__ int   g_tok[NE * TMAX];
__device__ int   g_slot[NE * TMAX];
__device__ float g_wt[NE * TMAX];
__device__ float g_psum[NE];

// ---------------- asm helpers ------------------------------------------------
__device__ __forceinline__ uint32_t smem_u32(const void* p) {
    uint32_t a;
    asm("{ .reg .u64 t; cvta.to.shared.u64 t, %1; cvt.u32.u64 %0, t; }" : "=r"(a) : "l"(p));
    return a;
}
#define CP16(dst, src) \
    asm volatile("cp.async.cg.shared.global [%0], [%1], 16;" :: "r"(dst), "l"(src) : "memory")
#define CPCOMMIT() asm volatile("cp.async.commit_group;" ::: "memory")
#define CPWAIT2()  asm volatile("cp.async.wait_group 2;" ::: "memory")

__device__ __forceinline__ void ldsm4(uint32_t* r, uint32_t addr) {
    asm volatile("ldmatrix.sync.aligned.m8n8.x4.shared.b16 {%0,%1,%2,%3}, [%4];"
        : "=r"(r[0]), "=r"(r[1]), "=r"(r[2]), "=r"(r[3]) : "r"(addr));
}
__device__ __forceinline__ void ldsm4t(uint32_t* r, uint32_t addr) {
    asm volatile("ldmatrix.sync.aligned.m8n8.x4.trans.shared.b16 {%0,%1,%2,%3}, [%4];"
        : "=r"(r[0]), "=r"(r[1]), "=r"(r[2]), "=r"(r[3]) : "r"(addr));
}
__device__ __forceinline__ void mma_f16(float* c, const uint32_t* a, const uint32_t* b) {
    asm volatile(
        "mma.sync.aligned.m16n8k16.row.col.f32.f16.f16.f32 "
        "{%0,%1,%2,%3}, {%4,%5,%6,%7}, {%8,%9}, {%0,%1,%2,%3};\n"
        : "+f"(c[0]), "+f"(c[1]), "+f"(c[2]), "+f"(c[3])
        : "r"(a[0]), "r"(a[1]), "r"(a[2]), "r"(a[3]), "r"(b[0]), "r"(b[1]));
}

// ---- fused prep: z=0 split x -> fp16 (+zero counters); z=1..6 weight conv ---
__global__ void k_prep(const float* __restrict__ x, int xn4,
                       const float* __restrict__ Wsg, const float* __restrict__ Wsu,
                       const float* __restrict__ Wsd, const float* __restrict__ Wg,
                       const float* __restrict__ Wu,  const float* __restrict__ Wd) {
    const int z = blockIdx.z;
    const float* in; __half* o; size_t n4;
    if (z == 0) {
        if (blockIdx.x == 0 && threadIdx.x < NE) {
            g_cnt[threadIdx.x] = 0; g_psum[threadIdx.x] = 0.f;
        }
        in = x; o = g_xh; n4 = (size_t)xn4;
    }
    else if (z == 1) { in = Wsg; o = g_Wsg16; n4 = (size_t)HD * DS / 4; }
    else if (z == 2) { in = Wsu; o = g_Wsu16; n4 = (size_t)HD * DS / 4; }
    else if (z == 3) { in = Wsd; o = g_Wsd16; n4 = (size_t)DS * HD / 4; }
    else if (z == 4) { in = Wg;  o = g_Wg16;  n4 = (size_t)NE * HD * DD / 4; }
    else if (z == 5) { in = Wu;  o = g_Wu16;  n4 = (size_t)NE * HD * DD / 4; }
    else             { in = Wd;  o = g_Wd16;  n4 = (size_t)NE * DD * HD / 4; }
    size_t i = (size_t)blockIdx.x * blockDim.x + threadIdx.x;
    size_t stride = (size_t)gridDim.x * blockDim.x;
    for (; i < n4; i += stride) {
        float4 v = ((const float4*)in)[i];
        __half2 h01 = __floats2half2_rn(v.x, v.y);
        __half2 h23 = __floats2half2_rn(v.z, v.w);
        ((uint2*)o)[i] = make_uint2(*(uint32_t*)&h01, *(uint32_t*)&h23);
    }
}

// ---------------- router ----------------------------------------------------
__global__ void k_router(const float* __restrict__ x, const float* __restrict__ Wr, int T) {
    __shared__ float s_p[NE];
    if (threadIdx.x < NE) s_p[threadIdx.x] = 0.f;
    __syncthreads();
    int warp = blockIdx.x * (blockDim.x >> 5) + (threadIdx.x >> 5);
    int lane = threadIdx.x & 31;
    if (warp < T) {
        int t = warp;
        const float* xr = x + (size_t)t * HD;
        float acc[NE];
        #pragma unroll
        for (int e = 0; e < NE; e++) acc[e] = 0.f;
        for (int i = lane; i < HD; i += 32) {
            float xv = xr[i];
            const float* w = Wr + (size_t)i * NE;
            #pragma unroll
            for (int e = 0; e < NE; e++) acc[e] += xv * w[e];
        }
        #pragma unroll
        for (int e = 0; e < NE; e++) {
            #pragma unroll
            for (int o = 16; o > 0; o >>= 1)
                acc[e] += __shfl_xor_sync(0xffffffffu, acc[e], o);
        }
        if (lane == 0) {
            float mx = acc[0];
            #pragma unroll
            for (int e = 1; e < NE; e++) mx = fmaxf(mx, acc[e]);
            float p[NE]; float s = 0.f;
            #pragma unroll
            for (int e = 0; e < NE; e++) { p[e] = expf(acc[e] - mx); s += p[e]; }
            float inv = 1.f / s;
            #pragma unroll
            for (int e = 0; e < NE; e++) p[e] *= inv;
            int i0 = 0;
            #pragma unroll
            for (int e = 1; e < NE; e++) if (p[e] > p[i0]) i0 = e;
            int i1 = (i0 == 0) ? 1 : 0;
            #pragma unroll
            for (int e = 0; e < NE; e++) if (e != i0 && p[e] > p[i1]) i1 = e;
            float w0 = p[i0], w1 = p[i1];
            float rn = 1.f / (w0 + w1);
            w0 *= rn; w1 *= rn;
            int pos0 = atomicAdd(&g_cnt[i0], 1);
            g_tok[i0 * TMAX + pos0]  = t;
            g_slot[i0 * TMAX + pos0] = t;
            g_wt[i0 * TMAX + pos0]   = w0;
            int pos1 = atomicAdd(&g_cnt[i1], 1);
            g_tok[i1 * TMAX + pos1]  = t;
            g_slot[i1 * TMAX + pos1] = T + t;
            g_wt[i1 * TMAX + pos1]   = w1;
            #pragma unroll
            for (int e = 0; e < NE; e++) atomicAdd(&s_p[e], p[e]);
        }
    }
    __syncthreads();
    if (threadIdx.x < NE) atomicAdd(&g_psum[threadIdx.x], s_p[threadIdx.x]);
}

// ------- merged gate+up GEMM + SwiGLU, 512 thr, tile 128x128 -----------------
__global__ __launch_bounds__(512, 1)
void k_gu_all(const __half* __restrict__ A_g, int T)
{
    const int z = blockIdx.z;
    int M, N, e = 0;
    bool gather;
    const __half *Bg, *Bu;
    __half* Ch;
    if (z == 0) {
        gather = false; M = T; N = DS;
        Bg = g_Wsg16; Bu = g_Wsu16;
        Ch = g_buf2H;
    } else {
        gather = true; e = z - 1;
        if (blockIdx.x >= DD / BN) return;
        M = g_cnt[e]; N = DD;
        size_t ws = (size_t)e * HD * DD;
        Bg = g_Wg16 + ws; Bu = g_Wu16 + ws;
        Ch = g_bufH + (size_t)e * TMAX * DD;
    }
    const int row0 = blockIdx.y * BM;
    if (row0 >= M) return;
    const int col0 = blockIdx.x * BN;
    const int K = HD;

    extern __shared__ char dsm[];
    const uint32_t sb = smem_u32(dsm);

    const int tid = threadIdx.x;
    const int wid = tid >> 5, lane = tid & 31;
    const int wm = wid & 3, wn = wid >> 2;
    const int g = lane >> 2, t4 = lane & 3;
    const int kswap = wid & 1;

    size_t aoff; uint32_t adst;
    {
        int r = tid >> 2, c16 = tid & 3;
        adst = r * (SA * 2) + c16 * 16;
        int gr = row0 + r;
        int grc = (gr < M) ? gr : (M - 1);
        if (gather) aoff = (size_t)g_tok[e * TMAX + grc] * K + c16 * 8;
        else        aoff = (size_t)grc * K + c16 * 8;
    }
    size_t boff; uint32_t bdst;
    {
        int br = tid >> 4, bc = tid & 15;
        bdst = br * (SB * 2) + bc * 16;
        boff = (size_t)br * N + col0 + bc * 8;
    }
    const size_t bstep = (size_t)BK * N;

    const int a_r = (lane & 7) + ((lane >> 3) & 1) * 8;
    const int a_c = ((lane >> 4) & 1) * 8;
    const uint32_t la = (uint32_t)(a_r * SA + a_c) * 2;
    const int b_k = (lane & 7) + ((lane >> 3) & 1) * 8;
    const int b_n = ((lane >> 4) & 1) * 8;
    const uint32_t lbT = (uint32_t)(b_k * SB + b_n) * 2;

    float accg[2][4][4], accu[2][4][4];
    #pragma unroll
    for (int mi = 0; mi < 2; mi++)
        #pragma unroll
        for (int ni = 0; ni < 4; ni++)
            #pragma unroll
            for (int q = 0; q < 4; q++) { accg[mi][ni][q] = 0.f; accu[mi][ni][q] = 0.f; }

    const int NC = K / BK;   // 32
    #pragma unroll
    for (int pc = 0; pc < 3; pc++) {
        uint32_t st = sb + pc * STG_GU;
        CP16(st + adst, A_g + aoff + (size_t)pc * BK);
        CP16(st + TILE_A + bdst, Bg + boff + (size_t)pc * bstep);
        CP16(st + TILE_A + TILE_BB + bdst, Bu + boff + (size_t)pc * bstep);
        CPCOMMIT();
    }

    int s_next = 3;
    for (int c = 0; c < NC; c++) {
        CPWAIT2();
        __syncthreads();
        {
            int nc3 = (c + 3 < NC) ? c + 3 : NC - 1;
            uint32_t st = sb + s_next * STG_GU;
            CP16(st + adst, A_g + aoff + (size_t)nc3 * BK);
            CP16(st + TILE_A + bdst, Bg + boff + (size_t)nc3 * bstep);
            CP16(st + TILE_A + TILE_BB + bdst, Bu + boff + (size_t)nc3 * bstep);
            CPCOMMIT();
        }
        s_next = (s_next + 1) & 3;
        const uint32_t st = sb + (c & 3) * STG_GU;
        #pragma unroll
        for (int kss = 0; kss < 2; kss++) {
            const int ks = kswap ? (1 - kss) : kss;
            uint32_t fA[2][4], fBg[2][4], fBu[2][4];
            #pragma unroll
            for (int mi = 0; mi < 2; mi++) {
                uint32_t ro = (uint32_t)((wm * 32 + mi * 16) * SA * 2) + ks * 32;
                ldsm4(fA[mi], st + ro + la);
            }
            #pragma unroll
            for (int nb = 0; nb < 2; nb++) {
                uint32_t bo = (uint32_t)(ks * 16 * SB * 2) + (uint32_t)((wn * 32 + nb * 16) * 2);
                ldsm4t(fBg[nb], st + TILE_A + bo + lbT);
                ldsm4t(fBu[nb], st + TILE_A + TILE_BB + bo + lbT);
            }
            #pragma unroll
            for (int mi = 0; mi < 2; mi++)
                #pragma unroll
                for (int ni = 0; ni < 4; ni++)
                    mma_f16(accg[mi][ni], fA[mi], &fBg[ni >> 1][(ni & 1) * 2]);
            #pragma unroll
            for (int mi = 0; mi < 2; mi++)
                #pragma unroll
                for (int ni = 0; ni < 4; ni++)
                    mma_f16(accu[mi][ni], fA[mi], &fBu[ni >> 1][(ni & 1) * 2]);
        }
    }

    // epilogue: swiglu (weighted if gather), single-fp16 store
    #pragma unroll
    for (int mi = 0; mi < 2; mi++) {
        int p0 = row0 + wm * 32 + mi * 16 + g;
        #pragma unroll
        for (int half = 0; half < 2; half++) {
            int p = p0 + half * 8;
            if (p >= M) continue;
            float w = gather ? g_wt[e * TMAX + p] : 1.f;
            size_t rowo = (size_t)p * N;
            #pragma unroll
            for (int ni = 0; ni < 4; ni++) {
                int col = col0 + wn * 32 + ni * 8 + 2 * t4;
                float gv0 = accg[mi][ni][half * 2 + 0];
                float gv1 = accg[mi][ni][half * 2 + 1];
                float uv0 = accu[mi][ni][half * 2 + 0];
                float uv1 = accu[mi][ni][half * 2 + 1];
                float v0 = w * (gv0 / (1.f + expf(-gv0))) * uv0;
                float v1 = w * (gv1 / (1.f + expf(-gv1))) * uv1;
                *(__half2*)(Ch + rowo + col) = __floats2half2_rn(v0, v1);
            }
        }
    }
}

// ------- merged down GEMM, 512 thr, tile 128x128, ks double-buffered ---------
__global__ __launch_bounds__(512, 1)
void k_dn_all(float* __restrict__ out, int T)
{
    const int z = blockIdx.z;
    int M, K, e = 0;
    bool scatter;
    const __half *A_g, *B;
    if (z == 0) {
        scatter = false; M = T; K = DS;
        A_g = g_buf2H;
        B = g_Wsd16;
    } else {
        scatter = true; e = z - 1;
        M = g_cnt[e]; K = DD;
        A_g = g_bufH + (size_t)e * TMAX * DD;
        B = g_Wd16 + (size_t)e * DD * HD;
    }
    const int row0 = blockIdx.y * BM;
    if (row0 >= M) return;
    const int col0 = blockIdx.x * BN;
    const int N = HD;

    extern __shared__ char dsm[];
    const uint32_t sb = smem_u32(dsm);

    const int tid = threadIdx.x;
    const int wid = tid >> 5, lane = tid & 31;
    const int wm = wid & 3, wn = wid >> 2;
    const int g = lane >> 2, t4 = lane & 3;

    size_t aoff; uint32_t adst;
    {
        int r = tid >> 2, c16 = tid & 3;
        adst = r * (SA * 2) + c16 * 16;
        int gr = row0 + r;
        int grc = (gr < M) ? gr : (M - 1);
        aoff = (size_t)grc * K + c16 * 8;
    }
    size_t boff; uint32_t bdst;
    {
        int br = tid >> 4, bc = tid & 15;
        bdst = br * (SB * 2) + bc * 16;
        boff = (size_t)br * N + col0 + bc * 8;
    }
    const size_t bstep = (size_t)BK * N;

    const int a_r = (lane & 7) + ((lane >> 3) & 1) * 8;
    const int a_c = ((lane >> 4) & 1) * 8;
    const uint32_t la = (uint32_t)(a_r * SA + a_c) * 2;
    const int b_k = (lane & 7) + ((lane >> 3) & 1) * 8;
    const int b_n = ((lane >> 4) & 1) * 8;
    const uint32_t lbT = (uint32_t)(b_k * SB + b_n) * 2;

    float acc[2][4][4];
    #pragma unroll
    for (int mi = 0; mi < 2; mi++)
        #pragma unroll
        for (int ni = 0; ni < 4; ni++)
            #pragma unroll
            for (int q = 0; q < 4; q++) acc[mi][ni][q] = 0.f;

    const int NC = K / BK;
    #pragma unroll
    for (int pc = 0; pc < 3; pc++) {
        uint32_t st = sb + pc * STG_DN;
        CP16(st + adst, A_g + aoff + (size_t)pc * BK);
        CP16(st + TILE_A + bdst, B + boff + (size_t)pc * bstep);
        CPCOMMIT();
    }

    int s_next = 3;
    for (int c = 0; c < NC; c++) {
        CPWAIT2();
        __syncthreads();
        {
            int nc3 = (c + 3 < NC) ? c + 3 : NC - 1;
            uint32_t st = sb + s_next * STG_DN;
            CP16(st + adst, A_g + aoff + (size_t)nc3 * BK);
            CP16(st + TILE_A + bdst, B + boff + (size_t)nc3 * bstep);
            CPCOMMIT();
        }
        s_next = (s_next + 1) & 3;
        const uint32_t st = sb + (c & 3) * STG_DN;

        // ks double buffer: LDSM(ks1) issued before MMAs(ks0) -> latency overlap
        uint32_t fA[2][2][4], fB[2][2][4];
        #pragma unroll
        for (int mi = 0; mi < 2; mi++) {
            uint32_t ro = (uint32_t)((wm * 32 + mi * 16) * SA * 2);
            ldsm4(fA[0][mi], st + ro + la);
        }
        #pragma unroll
        for (int nb = 0; nb < 2; nb++) {
            uint32_t bo = (uint32_t)((wn * 32 + nb * 16) * 2);
            ldsm4t(fB[0][nb], st + TILE_A + bo + lbT);
        }
        #pragma unroll
        for (int ks = 0; ks < 2; ks++) {
            if (ks == 0) {
                #pragma unroll
                for (int mi = 0; mi < 2; mi++) {
                    uint32_t ro = (uint32_t)((wm * 32 + mi * 16) * SA * 2) + 32;
                    ldsm4(fA[1][mi], st + ro + la);
                }
                #pragma unroll
                for (int nb = 0; nb < 2; nb++) {
                    uint32_t bo = (uint32_t)(16 * SB * 2) + (uint32_t)((wn * 32 + nb * 16) * 2);
                    ldsm4t(fB[1][nb], st + TILE_A + bo + lbT);
                }
            }
            #pragma unroll
            for (int mi = 0; mi < 2; mi++)
                #pragma unroll
                for (int ni = 0; ni < 4; ni++)
                    mma_f16(acc[mi][ni], fA[ks][mi], &fB[ks][ni >> 1][(ni & 1) * 2]);
        }
    }

    #pragma unroll
    for (int mi = 0; mi < 2; mi++) {
        int p0 = row0 + wm * 32 + mi * 16 + g;
        int p1 = p0 + 8;
        if (scatter) {
            __half* c0 = (p0 < M) ? g_routed + (size_t)g_slot[e * TMAX + p0] * HD : nullptr;
            __half* c1 = (p1 < M) ? g_routed + (size_t)g_slot[e * TMAX + p1] * HD : nullptr;
            #pragma unroll
            for (int ni = 0; ni < 4; ni++) {
                int col = col0 + wn * 32 + ni * 8 + 2 * t4;
                if (c0) *(__half2*)(c0 + col) = __floats2half2_rn(acc[mi][ni][0], acc[mi][ni][1]);
                if (c1) *(__half2*)(c1 + col) = __floats2half2_rn(acc[mi][ni][2], acc[mi][ni][3]);
            }
        } else {
            float* c0 = out + (size_t)p0 * HD;
            float* c1 = out + (size_t)p1 * HD;
            #pragma unroll
            for (int ni = 0; ni < 4; ni++) {
                int col = col0 + wn * 32 + ni * 8 + 2 * t4;
                *(float2*)(c0 + col) = make_float2(acc[mi][ni][0], acc[mi][ni][1]);
                *(float2*)(c1 + col) = make_float2(acc[mi][ni][2], acc[mi][ni][3]);
            }
        }
    }
}

// ---------------- final: out += routed slots (fp16); aux loss tail -----------
__global__ void k_final(float* __restrict__ out, int n4, int T, int out_size) {
    if (blockIdx.x == 0 && threadIdx.x == 0) {
        float a = 0.f;
        for (int e = 0; e < NE; e++) { float m = g_psum[e] / (float)T; a += m * m; }
        a *= (float)NE;
        for (size_t i = (size_t)T * HD; i < (size_t)out_size; i++) out[i] = a;
    }
    const uint2* r = (const uint2*)g_routed;
    float4* o4 = (float4*)out;
    int i = blockIdx.x * blockDim.x + threadIdx.x;
    int stride = gridDim.x * blockDim.x;
    for (; i < n4; i += stride) {
        float4 a = o4[i];
        uint2 b2 = r[i], c2 = r[i + n4];
        __half2 b01 = *(__half2*)&b2.x, b23 = *(__half2*)&b2.y;
        __half2 c01 = *(__half2*)&c2.x, c23 = *(__half2*)&c2.y;
        float2 fb01 = __half22float2(b01), fb23 = __half22float2(b23);
        float2 fc01 = __half22float2(c01), fc23 = __half22float2(c23);
        a.x += fb01.x + fc01.x;
        a.y += fb01.y + fc01.y;
        a.z += fb23.x + fc23.x;
        a.w += fb23.y + fc23.y;
        o4[i] = a;
    }
}

// ---------------- launch -----------------------------------------------------
extern "C" void kernel_launch(void* const* d_in, const int* in_sizes, int n_in,
                              void* d_out, int out_size) {
    const float* x   = (const float*)d_in[0];
    const float* Wr  = (const float*)d_in[1];
    const float* Wg  = (const float*)d_in[2];
    const float* Wu  = (const float*)d_in[3];
    const float* Wd  = (const float*)d_in[4];
    const float* Wsg = (const float*)d_in[5];
    const float* Wsu = (const float*)d_in[6];
    const float* Wsd = (const float*)d_in[7];
    float* out = (float*)d_out;
    const int T = in_sizes[0] / HD;   // 8192

    __half* xh;
    cudaGetSymbolAddress((void**)&xh, g_xh);

    cudaFuncSetAttribute(k_gu_all, cudaFuncAttributeMaxDynamicSharedMemorySize, SMEM_GU);
    cudaFuncSetAttribute(k_dn_all, cudaFuncAttributeMaxDynamicSharedMemorySize, SMEM_DN);

    // 0: fused prep — x->fp16 (+zero counters) and all weight converts
    k_prep<<<dim3(512, 1, 7), 256>>>(x, T * HD / 4, Wsg, Wsu, Wsd, Wg, Wu, Wd);
    // 1: router
    k_router<<<T / 8, 256>>>(x, Wr, T);
    // 2: merged gate+up (+swiglu)
    k_gu_all<<<dim3(DS / BN, T / BM, NE + 1), 512, SMEM_GU>>>(xh, T);
    // 3: merged down (ks double-buffered)
    k_dn_all<<<dim3(HD / BN, T / BM, NE + 1), 512, SMEM_DN>>>(out, T);
    // 4: combine + aux loss
    k_final<<<2048, 256>>>(out, (T * HD) / 4, T, out_size);
}

// round 17
// speedup vs baseline: 1.1516x; 1.0602x over previous
#include <cuda_runtime.h>
#include <cuda_fp16.h>
#include <math.h>
#include <stdint.h>

#define NE   8
#define HD   1024
#define DD   512
#define DS   1024
#define TMAX 8192

#define BM 128
#define BN 128
#define BK 32
#define SA 40                    // A: 16-bit elems per row (32 + 8 pad)
#define SB 136                   // B: 16-bit elems per row (128 + 8 pad)
#define TILE_A (128 * SA * 2)    // 10240 B
#define TILE_BB (32 * SB * 2)    // 8704 B
#define STG_GU (TILE_A + 2 * TILE_BB)   // A, Bg, Bu = 27648
#define STG_DN (TILE_A + TILE_BB)       // A, B = 18944
#define SMEM_GU (4 * STG_GU)     // 110592
#define SMEM_DN (4 * STG_DN)     // 75776 -> 2 CTAs/SM at 256 thr

// ---------------- scratch (static device globals; no allocations) ------------
__device__ __align__(16) __half g_xh[(size_t)TMAX * HD];
__device__ __align__(16) __half g_bufH[(size_t)NE * TMAX * DD];   // routed gu out
__device__ __align__(16) __half g_buf2H[(size_t)TMAX * DS];       // shared gu out
__device__ __align__(16) __half g_routed[(size_t)2 * TMAX * HD];  // fp16 slots
// fp16 weights in NATURAL [K][N] layout
__device__ __align__(16) __half g_Wsg16[(size_t)HD * DS];
__device__ __align__(16) __half g_Wsu16[(size_t)HD * DS];
__device__ __align__(16) __half g_Wsd16[(size_t)DS * HD];
__device__ __align__(16) __half g_Wg16[(size_t)NE * HD * DD];
__device__ __align__(16) __half g_Wu16[(size_t)NE * HD * DD];
__device__ __align__(16) __half g_Wd16[(size_t)NE * DD * HD];
__device__ int   g_cnt[NE];
__device__ int   g_tok[NE * TMAX];
__device__ int   g_slot[NE * TMAX];
__device__ float g_wt[NE * TMAX];
__device__ float g_psum[NE];

// ---------------- asm helpers ------------------------------------------------
__device__ __forceinline__ uint32_t smem_u32(const void* p) {
    uint32_t a;
    asm("{ .reg .u64 t; cvta.to.shared.u64 t, %1; cvt.u32.u64 %0, t; }" : "=r"(a) : "l"(p));
    return a;
}
#define CP16(dst, src) \
    asm volatile("cp.async.cg.shared.global [%0], [%1], 16;" :: "r"(dst), "l"(src) : "memory")
#define CPCOMMIT() asm volatile("cp.async.commit_group;" ::: "memory")
#define CPWAIT2()  asm volatile("cp.async.wait_group 2;" ::: "memory")

__device__ __forceinline__ void ldsm4(uint32_t* r, uint32_t addr) {
    asm volatile("ldmatrix.sync.aligned.m8n8.x4.shared.b16 {%0,%1,%2,%3}, [%4];"
        : "=r"(r[0]), "=r"(r[1]), "=r"(r[2]), "=r"(r[3]) : "r"(addr));
}
__device__ __forceinline__ void ldsm4t(uint32_t* r, uint32_t addr) {
    asm volatile("ldmatrix.sync.aligned.m8n8.x4.trans.shared.b16 {%0,%1,%2,%3}, [%4];"
        : "=r"(r[0]), "=r"(r[1]), "=r"(r[2]), "=r"(r[3]) : "r"(addr));
}
__device__ __forceinline__ void mma_f16(float* c, const uint32_t* a, const uint32_t* b) {
    asm volatile(
        "mma.sync.aligned.m16n8k16.row.col.f32.f16.f16.f32 "
        "{%0,%1,%2,%3}, {%4,%5,%6,%7}, {%8,%9}, {%0,%1,%2,%3};\n"
        : "+f"(c[0]), "+f"(c[1]), "+f"(c[2]), "+f"(c[3])
        : "r"(a[0]), "r"(a[1]), "r"(a[2]), "r"(a[3]), "r"(b[0]), "r"(b[1]));
}

// ---- fused prep: z=0 split x -> fp16 (+zero counters); z=1..6 weight conv ---
__global__ void k_prep(const float* __restrict__ x, int xn4,
                       const float* __restrict__ Wsg, const float* __restrict__ Wsu,
                       const float* __restrict__ Wsd, const float* __restrict__ Wg,
                       const float* __restrict__ Wu,  const float* __restrict__ Wd) {
    const int z = blockIdx.z;
    const float* in; __half* o; size_t n4;
    if (z == 0) {
        if (blockIdx.x == 0 && threadIdx.x < NE) {
            g_cnt[threadIdx.x] = 0; g_psum[threadIdx.x] = 0.f;
        }
        in = x; o = g_xh; n4 = (size_t)xn4;
    }
    else if (z == 1) { in = Wsg; o = g_Wsg16; n4 = (size_t)HD * DS / 4; }
    else if (z == 2) { in = Wsu; o = g_Wsu16; n4 = (size_t)HD * DS / 4; }
    else if (z == 3) { in = Wsd; o = g_Wsd16; n4 = (size_t)DS * HD / 4; }
    else if (z == 4) { in = Wg;  o = g_Wg16;  n4 = (size_t)NE * HD * DD / 4; }
    else if (z == 5) { in = Wu;  o = g_Wu16;  n4 = (size_t)NE * HD * DD / 4; }
    else             { in = Wd;  o = g_Wd16;  n4 = (size_t)NE * DD * HD / 4; }
    size_t i = (size_t)blockIdx.x * blockDim.x + threadIdx.x;
    size_t stride = (size_t)gridDim.x * blockDim.x;
    for (; i < n4; i += stride) {
        float4 v = ((const float4*)in)[i];
        __half2 h01 = __floats2half2_rn(v.x, v.y);
        __half2 h23 = __floats2half2_rn(v.z, v.w);
        ((uint2*)o)[i] = make_uint2(*(uint32_t*)&h01, *(uint32_t*)&h23);
    }
}

// ---------------- router ----------------------------------------------------
__global__ void k_router(const float* __restrict__ x, const float* __restrict__ Wr, int T) {
    __shared__ float s_p[NE];
    if (threadIdx.x < NE) s_p[threadIdx.x] = 0.f;
    __syncthreads();
    int warp = blockIdx.x * (blockDim.x >> 5) + (threadIdx.x >> 5);
    int lane = threadIdx.x & 31;
    if (warp < T) {
        int t = warp;
        const float* xr = x + (size_t)t * HD;
        float acc[NE];
        #pragma unroll
        for (int e = 0; e < NE; e++) acc[e] = 0.f;
        for (int i = lane; i < HD; i += 32) {
            float xv = xr[i];
            const float* w = Wr + (size_t)i * NE;
            #pragma unroll
            for (int e = 0; e < NE; e++) acc[e] += xv * w[e];
        }
        #pragma unroll
        for (int e = 0; e < NE; e++) {
            #pragma unroll
            for (int o = 16; o > 0; o >>= 1)
                acc[e] += __shfl_xor_sync(0xffffffffu, acc[e], o);
        }
        if (lane == 0) {
            float mx = acc[0];
            #pragma unroll
            for (int e = 1; e < NE; e++) mx = fmaxf(mx, acc[e]);
            float p[NE]; float s = 0.f;
            #pragma unroll
            for (int e = 0; e < NE; e++) { p[e] = expf(acc[e] - mx); s += p[e]; }
            float inv = 1.f / s;
            #pragma unroll
            for (int e = 0; e < NE; e++) p[e] *= inv;
            int i0 = 0;
            #pragma unroll
            for (int e = 1; e < NE; e++) if (p[e] > p[i0]) i0 = e;
            int i1 = (i0 == 0) ? 1 : 0;
            #pragma unroll
            for (int e = 0; e < NE; e++) if (e != i0 && p[e] > p[i1]) i1 = e;
            float w0 = p[i0], w1 = p[i1];
            float rn = 1.f / (w0 + w1);
            w0 *= rn; w1 *= rn;
            int pos0 = atomicAdd(&g_cnt[i0], 1);
            g_tok[i0 * TMAX + pos0]  = t;
            g_slot[i0 * TMAX + pos0] = t;
            g_wt[i0 * TMAX + pos0]   = w0;
            int pos1 = atomicAdd(&g_cnt[i1], 1);
            g_tok[i1 * TMAX + pos1]  = t;
            g_slot[i1 * TMAX + pos1] = T + t;
            g_wt[i1 * TMAX + pos1]   = w1;
            #pragma unroll
            for (int e = 0; e < NE; e++) atomicAdd(&s_p[e], p[e]);
        }
    }
    __syncthreads();
    if (threadIdx.x < NE) atomicAdd(&g_psum[threadIdx.x], s_p[threadIdx.x]);
}

// ------- merged gate+up GEMM + SwiGLU, 512 thr, tile 128x128 (unchanged) -----
__global__ __launch_bounds__(512, 1)
void k_gu_all(const __half* __restrict__ A_g, int T)
{
    const int z = blockIdx.z;
    int M, N, e = 0;
    bool gather;
    const __half *Bg, *Bu;
    __half* Ch;
    if (z == 0) {
        gather = false; M = T; N = DS;
        Bg = g_Wsg16; Bu = g_Wsu16;
        Ch = g_buf2H;
    } else {
        gather = true; e = z - 1;
        if (blockIdx.x >= DD / BN) return;
        M = g_cnt[e]; N = DD;
        size_t ws = (size_t)e * HD * DD;
        Bg = g_Wg16 + ws; Bu = g_Wu16 + ws;
        Ch = g_bufH + (size_t)e * TMAX * DD;
    }
    const int row0 = blockIdx.y * BM;
    if (row0 >= M) return;
    const int col0 = blockIdx.x * BN;
    const int K = HD;

    extern __shared__ char dsm[];
    const uint32_t sb = smem_u32(dsm);

    const int tid = threadIdx.x;
    const int wid = tid >> 5, lane = tid & 31;
    const int wm = wid & 3, wn = wid >> 2;
    const int g = lane >> 2, t4 = lane & 3;
    const int kswap = wid & 1;

    size_t aoff; uint32_t adst;
    {
        int r = tid >> 2, c16 = tid & 3;
        adst = r * (SA * 2) + c16 * 16;
        int gr = row0 + r;
        int grc = (gr < M) ? gr : (M - 1);
        if (gather) aoff = (size_t)g_tok[e * TMAX + grc] * K + c16 * 8;
        else        aoff = (size_t)grc * K + c16 * 8;
    }
    size_t boff; uint32_t bdst;
    {
        int br = tid >> 4, bc = tid & 15;
        bdst = br * (SB * 2) + bc * 16;
        boff = (size_t)br * N + col0 + bc * 8;
    }
    const size_t bstep = (size_t)BK * N;

    const int a_r = (lane & 7) + ((lane >> 3) & 1) * 8;
    const int a_c = ((lane >> 4) & 1) * 8;
    const uint32_t la = (uint32_t)(a_r * SA + a_c) * 2;
    const int b_k = (lane & 7) + ((lane >> 3) & 1) * 8;
    const int b_n = ((lane >> 4) & 1) * 8;
    const uint32_t lbT = (uint32_t)(b_k * SB + b_n) * 2;

    float accg[2][4][4], accu[2][4][4];
    #pragma unroll
    for (int mi = 0; mi < 2; mi++)
        #pragma unroll
        for (int ni = 0; ni < 4; ni++)
            #pragma unroll
            for (int q = 0; q < 4; q++) { accg[mi][ni][q] = 0.f; accu[mi][ni][q] = 0.f; }

    const int NC = K / BK;   // 32
    #pragma unroll
    for (int pc = 0; pc < 3; pc++) {
        uint32_t st = sb + pc * STG_GU;
        CP16(st + adst, A_g + aoff + (size_t)pc * BK);
        CP16(st + TILE_A + bdst, Bg + boff + (size_t)pc * bstep);
        CP16(st + TILE_A + TILE_BB + bdst, Bu + boff + (size_t)pc * bstep);
        CPCOMMIT();
    }

    int s_next = 3;
    for (int c = 0; c < NC; c++) {
        CPWAIT2();
        __syncthreads();
        {
            int nc3 = (c + 3 < NC) ? c + 3 : NC - 1;
            uint32_t st = sb + s_next * STG_GU;
            CP16(st + adst, A_g + aoff + (size_t)nc3 * BK);
            CP16(st + TILE_A + bdst, Bg + boff + (size_t)nc3 * bstep);
            CP16(st + TILE_A + TILE_BB + bdst, Bu + boff + (size_t)nc3 * bstep);
            CPCOMMIT();
        }
        s_next = (s_next + 1) & 3;
        const uint32_t st = sb + (c & 3) * STG_GU;
        #pragma unroll
        for (int kss = 0; kss < 2; kss++) {
            const int ks = kswap ? (1 - kss) : kss;
            uint32_t fA[2][4], fBg[2][4], fBu[2][4];
            #pragma unroll
            for (int mi = 0; mi < 2; mi++) {
                uint32_t ro = (uint32_t)((wm * 32 + mi * 16) * SA * 2) + ks * 32;
                ldsm4(fA[mi], st + ro + la);
            }
            #pragma unroll
            for (int nb = 0; nb < 2; nb++) {
                uint32_t bo = (uint32_t)(ks * 16 * SB * 2) + (uint32_t)((wn * 32 + nb * 16) * 2);
                ldsm4t(fBg[nb], st + TILE_A + bo + lbT);
                ldsm4t(fBu[nb], st + TILE_A + TILE_BB + bo + lbT);
            }
            #pragma unroll
            for (int mi = 0; mi < 2; mi++)
                #pragma unroll
                for (int ni = 0; ni < 4; ni++)
                    mma_f16(accg[mi][ni], fA[mi], &fBg[ni >> 1][(ni & 1) * 2]);
            #pragma unroll
            for (int mi = 0; mi < 2; mi++)
                #pragma unroll
                for (int ni = 0; ni < 4; ni++)
                    mma_f16(accu[mi][ni], fA[mi], &fBu[ni >> 1][(ni & 1) * 2]);
        }
    }

    // epilogue: swiglu (weighted if gather), single-fp16 store
    #pragma unroll
    for (int mi = 0; mi < 2; mi++) {
        int p0 = row0 + wm * 32 + mi * 16 + g;
        #pragma unroll
        for (int half = 0; half < 2; half++) {
            int p = p0 + half * 8;
            if (p >= M) continue;
            float w = gather ? g_wt[e * TMAX + p] : 1.f;
            size_t rowo = (size_t)p * N;
            #pragma unroll
            for (int ni = 0; ni < 4; ni++) {
                int col = col0 + wn * 32 + ni * 8 + 2 * t4;
                float gv0 = accg[mi][ni][half * 2 + 0];
                float gv1 = accg[mi][ni][half * 2 + 1];
                float uv0 = accu[mi][ni][half * 2 + 0];
                float uv1 = accu[mi][ni][half * 2 + 1];
                float v0 = w * (gv0 / (1.f + expf(-gv0))) * uv0;
                float v1 = w * (gv1 / (1.f + expf(-gv1))) * uv1;
                *(__half2*)(Ch + rowo + col) = __floats2half2_rn(v0, v1);
            }
        }
    }
}

// ------- merged down GEMM: 256 thr, warp tile 64x32, 2 CTAs/SM ---------------
__global__ __launch_bounds__(256, 2)
void k_dn_all(float* __restrict__ out, int T)
{
    const int z = blockIdx.z;
    int M, K, e = 0;
    bool scatter;
    const __half *A_g, *B;
    if (z == 0) {
        scatter = false; M = T; K = DS;
        A_g = g_buf2H;
        B = g_Wsd16;
    } else {
        scatter = true; e = z - 1;
        M = g_cnt[e]; K = DD;
        A_g = g_bufH + (size_t)e * TMAX * DD;
        B = g_Wd16 + (size_t)e * DD * HD;
    }
    const int row0 = blockIdx.y * BM;
    if (row0 >= M) return;
    const int col0 = blockIdx.x * BN;
    const int N = HD;

    extern __shared__ char dsm[];
    const uint32_t sb = smem_u32(dsm);

    const int tid = threadIdx.x;
    const int wid = tid >> 5, lane = tid & 31;   // 8 warps
    const int wm = wid >> 2, wn = wid & 3;       // 2x4 grid, 64x32 warp tiles
    const int g = lane >> 2, t4 = lane & 3;

    // A cp.async: 2 chunks/thread (128 rows x 4 chunks of 16B, 256 threads)
    size_t aoff; uint32_t adst;
    {
        int r = tid >> 1, c16 = (tid & 1) * 2;
        adst = r * (SA * 2) + c16 * 16;
        int gr = row0 + r;
        int grc = (gr < M) ? gr : (M - 1);
        aoff = (size_t)grc * K + c16 * 8;
    }
    // B cp.async: 2 chunks/thread (32 rows x 16 chunks, 256 threads)
    size_t boff; uint32_t bdst;
    {
        int br = tid >> 3, bc = tid & 7;
        bdst = br * (SB * 2) + bc * 16;
        boff = (size_t)br * N + col0 + bc * 8;
    }
    const size_t bstep = (size_t)BK * N;

    const int a_r = (lane & 7) + ((lane >> 3) & 1) * 8;
    const int a_c = ((lane >> 4) & 1) * 8;
    const uint32_t la = (uint32_t)(a_r * SA + a_c) * 2;
    const int b_k = (lane & 7) + ((lane >> 3) & 1) * 8;
    const int b_n = ((lane >> 4) & 1) * 8;
    const uint32_t lbT = (uint32_t)(b_k * SB + b_n) * 2;

    float acc[4][4][4];
    #pragma unroll
    for (int mi = 0; mi < 4; mi++)
        #pragma unroll
        for (int ni = 0; ni < 4; ni++)
            #pragma unroll
            for (int q = 0; q < 4; q++) acc[mi][ni][q] = 0.f;

    const int NC = K / BK;
    #pragma unroll
    for (int pc = 0; pc < 3; pc++) {
        uint32_t st = sb + pc * STG_DN;
        size_t ko = (size_t)pc * BK;
        CP16(st + adst, A_g + aoff + ko);
        CP16(st + adst + 16, A_g + aoff + 8 + ko);
        CP16(st + TILE_A + bdst, B + boff + (size_t)pc * bstep);
        CP16(st + TILE_A + bdst + 128, B + boff + 64 + (size_t)pc * bstep);
        CPCOMMIT();
    }

    int s_next = 3;
    for (int c = 0; c < NC; c++) {
        CPWAIT2();
        __syncthreads();
        {
            int nc3 = (c + 3 < NC) ? c + 3 : NC - 1;
            uint32_t st = sb + s_next * STG_DN;
            size_t ko = (size_t)nc3 * BK;
            CP16(st + adst, A_g + aoff + ko);
            CP16(st + adst + 16, A_g + aoff + 8 + ko);
            CP16(st + TILE_A + bdst, B + boff + (size_t)nc3 * bstep);
            CP16(st + TILE_A + bdst + 128, B + boff + 64 + (size_t)nc3 * bstep);
            CPCOMMIT();
        }
        s_next = (s_next + 1) & 3;
        const uint32_t st = sb + (c & 3) * STG_DN;
        #pragma unroll
        for (int ks = 0; ks < 2; ks++) {
            uint32_t fA[4][4], fB[2][4];
            #pragma unroll
            for (int mi = 0; mi < 4; mi++) {
                uint32_t ro = (uint32_t)((wm * 64 + mi * 16) * SA * 2) + ks * 32;
                ldsm4(fA[mi], st + ro + la);
            }
            #pragma unroll
            for (int nb = 0; nb < 2; nb++) {
                uint32_t bo = (uint32_t)(ks * 16 * SB * 2) + (uint32_t)((wn * 32 + nb * 16) * 2);
                ldsm4t(fB[nb], st + TILE_A + bo + lbT);
            }
            #pragma unroll
            for (int mi = 0; mi < 4; mi++)
                #pragma unroll
                for (int ni = 0; ni < 4; ni++)
                    mma_f16(acc[mi][ni], fA[mi], &fB[ni >> 1][(ni & 1) * 2]);
        }
    }

    #pragma unroll
    for (int mi = 0; mi < 4; mi++) {
        int p0 = row0 + wm * 64 + mi * 16 + g;
        int p1 = p0 + 8;
        if (scatter) {
            __half* c0 = (p0 < M) ? g_routed + (size_t)g_slot[e * TMAX + p0] * HD : nullptr;
            __half* c1 = (p1 < M) ? g_routed + (size_t)g_slot[e * TMAX + p1] * HD : nullptr;
            #pragma unroll
            for (int ni = 0; ni < 4; ni++) {
                int col = col0 + wn * 32 + ni * 8 + 2 * t4;
                if (c0) *(__half2*)(c0 + col) = __floats2half2_rn(acc[mi][ni][0], acc[mi][ni][1]);
                if (c1) *(__half2*)(c1 + col) = __floats2half2_rn(acc[mi][ni][2], acc[mi][ni][3]);
            }
        } else {
            float* c0 = out + (size_t)p0 * HD;
            float* c1 = out + (size_t)p1 * HD;
            #pragma unroll
            for (int ni = 0; ni < 4; ni++) {
                int col = col0 + wn * 32 + ni * 8 + 2 * t4;
                *(float2*)(c0 + col) = make_float2(acc[mi][ni][0], acc[mi][ni][1]);
                *(float2*)(c1 + col) = make_float2(acc[mi][ni][2], acc[mi][ni][3]);
            }
        }
    }
}

// ---------------- final: out += routed slots (fp16); aux loss tail -----------
__global__ void k_final(float* __restrict__ out, int n4, int T, int out_size) {
    if (blockIdx.x == 0 && threadIdx.x == 0) {
        float a = 0.f;
        for (int e = 0; e < NE; e++) { float m = g_psum[e] / (float)T; a += m * m; }
        a *= (float)NE;
        for (size_t i = (size_t)T * HD; i < (size_t)out_size; i++) out[i] = a;
    }
    const uint2* r = (const uint2*)g_routed;
    float4* o4 = (float4*)out;
    int i = blockIdx.x * blockDim.x + threadIdx.x;
    int stride = gridDim.x * blockDim.x;
    for (; i < n4; i += stride) {
        float4 a = o4[i];
        uint2 b2 = r[i], c2 = r[i + n4];
        __half2 b01 = *(__half2*)&b2.x, b23 = *(__half2*)&b2.y;
        __half2 c01 = *(__half2*)&c2.x, c23 = *(__half2*)&c2.y;
        float2 fb01 = __half22float2(b01), fb23 = __half22float2(b23);
        float2 fc01 = __half22float2(c01), fc23 = __half22float2(c23);
        a.x += fb01.x + fc01.x;
        a.y += fb01.y + fc01.y;
        a.z += fb23.x + fc23.x;
        a.w += fb23.y + fc23.y;
        o4[i] = a;
    }
}

// ---------------- launch -----------------------------------------------------
extern "C" void kernel_launch(void* const* d_in, const int* in_sizes, int n_in,
                              void* d_out, int out_size) {
    const float* x   = (const float*)d_in[0];
    const float* Wr  = (const float*)d_in[1];
    const float* Wg  = (const float*)d_in[2];
    const float* Wu  = (const float*)d_in[3];
    const float* Wd  = (const float*)d_in[4];
    const float* Wsg = (const float*)d_in[5];
    const float* Wsu = (const float*)d_in[6];
    const float* Wsd = (const float*)d_in[7];
    float* out = (float*)d_out;
    const int T = in_sizes[0] / HD;   // 8192

    __half* xh;
    cudaGetSymbolAddress((void**)&xh, g_xh);

    cudaFuncSetAttribute(k_gu_all, cudaFuncAttributeMaxDynamicSharedMemorySize, SMEM_GU);
    cudaFuncSetAttribute(k_dn_all, cudaFuncAttributeMaxDynamicSharedMemorySize, SMEM_DN);

    // 0: fused prep — x->fp16 (+zero counters) and all weight converts
    k_prep<<<dim3(512, 1, 7), 256>>>(x, T * HD / 4, Wsg, Wsu, Wsd, Wg, Wu, Wd);
    // 1: router
    k_router<<<T / 8, 256>>>(x, Wr, T);
    // 2: merged gate+up (+swiglu)
    k_gu_all<<<dim3(DS / BN, T / BM, NE + 1), 512, SMEM_GU>>>(xh, T);
    // 3: merged down — 256 thr, 64x32 warp tiles, 2 CTAs/SM
    k_dn_all<<<dim3(HD / BN, T / BM, NE + 1), 256, SMEM_DN>>>(out, T);
    // 4: combine + aux loss
    k_final<<<2048, 256>>>(out, (T * HD) / 4, T, out_size);
}